// round 12
// baseline (speedup 1.0000x reference)
#include <cuda_runtime.h>
#include <cuda_fp16.h>
#include <cstdint>

#define B    2048
#define NC   32
#define M    496
#define H1   64
#define H2   32
#define CLS  10
#define EPS  1e-5f
#define MPB  16                // modules per block
#define NMC  (M / MPB)         // 31 module-chunks
#define BT   128               // batch rows per block
#define MSPLIT 16
#define MCHUNK (M / MSPLIT)    // 31

#define WSTR 36                // A-tile row stride in words (conflict-free frags)

// ---- smem layout (bytes) ----
#define A_B   0                // 128 rows * 144B = 18432
#define BF_B  18432            // B frag store: 16 units * 264B = 4224
#define ABC_B 22656            // 64 * float4
#define DEW_B 23680            // 32 * float4
#define B3_B  24192
#define SMEM_SZ 24196

#define A_W  (A_B/4)
#define BF_W (BF_B/4)

// Per-module outputs, transposed: g_ot[m*B + b]
__device__ float g_ot[M * B];

static __device__ __forceinline__ uint32_t f16x2(float hi, float lo) {
    uint32_t r;
    asm("cvt.rn.f16x2.f32 %0, %1, %2;" : "=r"(r) : "f"(hi), "f"(lo));
    return r;   // hi -> [31:16], lo -> [15:0]
}

static __device__ __forceinline__ uint32_t smem_u32(const void* p) {
    uint32_t a;
    asm("{ .reg .u64 t; cvta.to.shared.u64 t, %1; cvt.u32.u64 %0, t; }"
        : "=r"(a) : "l"(p));
    return a;
}

static __device__ __forceinline__ void ldsm_x4(uint32_t& r0, uint32_t& r1,
                                               uint32_t& r2, uint32_t& r3,
                                               uint32_t addr) {
    asm volatile("ldmatrix.sync.aligned.m8n8.x4.shared.b16 {%0,%1,%2,%3}, [%4];"
                 : "=r"(r0), "=r"(r1), "=r"(r2), "=r"(r3) : "r"(addr));
}

static __device__ __forceinline__ void mma16816(float c[4],
    uint32_t a0, uint32_t a1, uint32_t a2, uint32_t a3,
    uint32_t b0, uint32_t b1)
{
    asm volatile(
        "mma.sync.aligned.m16n8k16.row.col.f32.f16.f16.f32 "
        "{%0,%1,%2,%3}, {%4,%5,%6,%7}, {%8,%9}, {%0,%1,%2,%3};"
        : "+f"(c[0]), "+f"(c[1]), "+f"(c[2]), "+f"(c[3])
        : "r"(a0), "r"(a1), "r"(a2), "r"(a3), "r"(b0), "r"(b1));
}

static __device__ __forceinline__ void adv_pair(int& i, int& j) {
    if (++j == NC) { ++i; j = i + 1; }
}

__global__ __launch_bounds__(256, 4) void nam_mma_kernel(
    const float* __restrict__ x,
    const float* __restrict__ W1, const float* __restrict__ b1,
    const float* __restrict__ g1, const float* __restrict__ be1,
    const float* __restrict__ m1, const float* __restrict__ v1,
    const float* __restrict__ W2, const float* __restrict__ b2,
    const float* __restrict__ g2, const float* __restrict__ be2,
    const float* __restrict__ m2, const float* __restrict__ v2,
    const float* __restrict__ W3, const float* __restrict__ b3,
    const float* __restrict__ bout,
    float* __restrict__ out)
{
    __shared__ __align__(16) unsigned char sm[SMEM_SZ];
    uint32_t* smw = (uint32_t*)sm;

    const int tid  = threadIdx.x;
    const int lane = tid & 31;
    const int w    = tid >> 5;          // warp 0..7 -> rows 16w..16w+15
    const int gid  = lane >> 2;         // 0..7
    const int tig  = lane & 3;          // 0..3
    const int yoff = blockIdx.y * BT;
    const int mc   = blockIdx.x;
    const int m0   = mc * MPB;

    const int hrow = tid & 127;         // h1 row this thread computes
    const int kh   = tid >> 7;          // k half (0: k<32, 1: k>=32)
    const int bh   = yoff + hrow;

    // Fold out-init into this kernel (out is poisoned by the harness).
    if (blockIdx.x == 0 && tid < BT) {
        #pragma unroll
        for (int c = 0; c < CLS; c++) out[(yoff + tid) * CLS + c] = bout[c];
    }

    // ldmatrix lane base: mat0 rows 0-7/k0-7, mat1 rows 8-15/k0-7,
    // mat2 rows 0-7/k8-15, mat3 rows 8-15/k8-15
    const int lrow = 16*w + (lane & 7) + ((lane & 8) ? 8 : 0);
    const uint32_t a_lbase =
        smem_u32(smw + A_W + lrow * WSTR + ((lane & 16) ? 4 : 0));

    // ---- staging roles (prefetch registers) ----
    const bool rABC  = tid < H1;
    const bool rDEW  = tid >= H1 && tid < H1 + H2;
    const bool rB3   = tid == H1 + H2;
    float2 pw[4];
    float  st[7];

    // pair indices for m0 (all threads, uniform)
    int ci = 0, cj;
    { int rem = m0, i = 0;
      while (rem >= NC - 1 - i) { rem -= NC - 1 - i; i++; }
      ci = i; cj = i + 1 + rem; }

    // prologue: issue loads for module m0
    {
        const float2* w2p = (const float2*)(W2 + m0 * (H2 * H1));
        #pragma unroll
        for (int r = 0; r < 4; r++) pw[r] = w2p[tid + r * 256];
        if (rABC) {
            const int o = tid;
            st[0] = g1[m0*H1 + o]; st[1] = v1[m0*H1 + o];
            st[2] = W1[(m0*H1 + o)*2]; st[3] = W1[(m0*H1 + o)*2 + 1];
            st[4] = b1[m0*H1 + o]; st[5] = m1[m0*H1 + o]; st[6] = be1[m0*H1 + o];
        } else if (rDEW) {
            const int o = tid - H1;
            st[0] = g2[m0*H2 + o]; st[1] = v2[m0*H2 + o];
            st[2] = b2[m0*H2 + o]; st[3] = m2[m0*H2 + o];
            st[4] = be2[m0*H2 + o]; st[5] = W3[m0*H2 + o];
        } else if (rB3) {
            st[0] = b3[m0];
        }
    }
    float xa = x[bh * NC + ci];
    float xb = x[bh * NC + cj];

    for (int mi = 0; mi < MPB; mi++) {
        const int m = m0 + mi;

        // ==== commit staged registers -> smem (fp16) ====
        #pragma unroll
        for (int r = 0; r < 4; r++) {
            const int p  = tid + r * 256;     // pair index: o = p>>5, pk = p&31
            const int o  = p >> 5;
            const int pk = p & 31;
            const int ks   = pk >> 3;
            const int wtig = pk & 3;
            const int slot = (pk >> 2) & 1;
            const int nt   = o >> 3;
            const int go   = o & 7;
            const float2 wv = pw[r];
            const int elem = 8*go + 2*wtig + slot;
            smw[BF_W + (ks*4 + nt)*66 + elem] = f16x2(wv.y, wv.x);
        }
        if (rABC) {
            const float s = st[0] * rsqrtf(st[1] + EPS);
            ((float4*)(sm + ABC_B))[tid] = make_float4(
                s * st[2], s * st[3], s * (st[4] - st[5]) + st[6], 0.0f);
        } else if (rDEW) {
            const float s = st[0] * rsqrtf(st[1] + EPS);
            ((float4*)(sm + DEW_B))[tid - H1] = make_float4(
                s, s * (st[2] - st[3]) + st[4], st[5], 0.0f);
        } else if (rB3) {
            *(float*)(sm + B3_B) = st[0];
        }
        __syncthreads();   // smem staged (B frags, ABC, DEW, b3)

        // ==== layer1 (fp32) -> A tile (fp16) ====
        {
            const float4* ABC = (const float4*)(sm + ABC_B);
            #pragma unroll
            for (int q = 0; q < 4; q++) {
                uint32_t w4[4];
                #pragma unroll
                for (int j = 0; j < 4; j++) {
                    const int k0 = 32*kh + 2*(4*q + j);
                    const float4 c0 = ABC[k0];
                    const float4 c1 = ABC[k0 + 1];
                    const float h0 = fmaxf(fmaf(c0.x, xa, fmaf(c0.y, xb, c0.z)), 0.0f);
                    const float h1 = fmaxf(fmaf(c1.x, xa, fmaf(c1.y, xb, c1.z)), 0.0f);
                    w4[j] = f16x2(h1, h0);
                }
                const int word = hrow * WSTR + 16*kh + 4*q;
                *((uint4*)(smw + A_W + word)) = make_uint4(w4[0], w4[1], w4[2], w4[3]);
            }
        }

        // ==== prefetch module mi+1 (overlaps barrier + MMA below) ====
        float xan = 0.0f, xbn = 0.0f;
        if (mi + 1 < MPB) {
            const int mn = m + 1;
            adv_pair(ci, cj);
            xan = x[bh * NC + ci];
            xbn = x[bh * NC + cj];
            const float2* w2p = (const float2*)(W2 + mn * (H2 * H1));
            #pragma unroll
            for (int r = 0; r < 4; r++) pw[r] = w2p[tid + r * 256];
            if (rABC) {
                const int o = tid;
                st[0] = g1[mn*H1 + o]; st[1] = v1[mn*H1 + o];
                st[2] = W1[(mn*H1 + o)*2]; st[3] = W1[(mn*H1 + o)*2 + 1];
                st[4] = b1[mn*H1 + o]; st[5] = m1[mn*H1 + o]; st[6] = be1[mn*H1 + o];
            } else if (rDEW) {
                const int o = tid - H1;
                st[0] = g2[mn*H2 + o]; st[1] = v2[mn*H2 + o];
                st[2] = b2[mn*H2 + o]; st[3] = m2[mn*H2 + o];
                st[4] = be2[mn*H2 + o]; st[5] = W3[mn*H2 + o];
            } else if (rB3) {
                st[0] = b3[mn];
            }
        }
        __syncthreads();   // A tile ready

        // ==== MMA: warp w owns rows [16w, 16w+16), 16 HMMA/module ====
        float cf[4][4];
        #pragma unroll
        for (int nt = 0; nt < 4; nt++)
            #pragma unroll
            for (int j = 0; j < 4; j++) cf[nt][j] = 0.0f;

        #pragma unroll
        for (int ks = 0; ks < 4; ks++) {
            uint32_t a0, a1, a2, a3;
            ldsm_x4(a0, a1, a2, a3, a_lbase + ks * 32);
            uint2 bf[4];
            #pragma unroll
            for (int nt = 0; nt < 4; nt++)
                bf[nt] = *((const uint2*)(smw + BF_W + (ks*4 + nt)*66 + lane*2));
            #pragma unroll
            for (int nt = 0; nt < 4; nt++)
                mma16816(cf[nt], a0, a1, a2, a3, bf[nt].x, bf[nt].y);
        }

        // ==== epilogue: BN2 + ReLU + W3, row-reduce, write g_ot ====
        const float4* DEW = (const float4*)(sm + DEW_B);
        float p0 = 0.0f, p1 = 0.0f;
        #pragma unroll
        for (int nt = 0; nt < 4; nt++) {
            const int n0 = 8*nt + 2*tig;
            const float4 d0 = DEW[n0];
            const float4 d1 = DEW[n0 + 1];
            p0 = fmaf(d0.z, fmaxf(fmaf(d0.x, cf[nt][0], d0.y), 0.0f), p0);
            p0 = fmaf(d1.z, fmaxf(fmaf(d1.x, cf[nt][1], d1.y), 0.0f), p0);
            p1 = fmaf(d0.z, fmaxf(fmaf(d0.x, cf[nt][2], d0.y), 0.0f), p1);
            p1 = fmaf(d1.z, fmaxf(fmaf(d1.x, cf[nt][3], d1.y), 0.0f), p1);
        }
        p0 += __shfl_xor_sync(0xffffffffu, p0, 1);
        p0 += __shfl_xor_sync(0xffffffffu, p0, 2);
        p1 += __shfl_xor_sync(0xffffffffu, p1, 1);
        p1 += __shfl_xor_sync(0xffffffffu, p1, 2);

        if (tig == 0) {
            const float b3s = *(const float*)(sm + B3_B);
            const int r0 = yoff + 16*w + gid;
            g_ot[m * B + r0]     = b3s + p0;
            g_ot[m * B + r0 + 8] = b3s + p1;
        }
        __syncthreads();   // all smem reads done before next commit overwrites

        xa = xan; xb = xbn;
    }
}

// Head: grid (B/256, MSPLIT). Thread = one b; reads 31 g values once each,
// accumulates all 10 classes in registers, then 10 low-duplication atomics.
__global__ __launch_bounds__(256) void nam_head_kernel(
    const float* __restrict__ Wout,   // [CLS, M]
    float* __restrict__ out)          // [B, CLS]
{
    const int tid = threadIdx.x;
    const int b   = blockIdx.x * 256 + tid;
    const int m0  = blockIdx.y * MCHUNK;

    __shared__ float ws[MCHUNK * CLS];   // ws[j][c] = Wout[c][m0+j]
    for (int i = tid; i < MCHUNK * CLS; i += 256) {
        const int j = i / CLS;
        const int c = i % CLS;
        ws[i] = Wout[c * M + m0 + j];
    }
    __syncthreads();

    float acc[CLS];
    #pragma unroll
    for (int c = 0; c < CLS; c++) acc[c] = 0.0f;

    const float* __restrict__ gcol = g_ot + m0 * B + b;
    #pragma unroll
    for (int j = 0; j < MCHUNK; j++) {
        const float g = gcol[j * B];             // coalesced LDG
        #pragma unroll
        for (int c = 0; c < CLS; c++)
            acc[c] = fmaf(g, ws[j * CLS + c], acc[c]);   // smem broadcast
    }

    #pragma unroll
    for (int c = 0; c < CLS; c++)
        atomicAdd(&out[b * CLS + c], acc[c]);
}

extern "C" void kernel_launch(void* const* d_in, const int* in_sizes, int n_in,
                              void* d_out, int out_size)
{
    // metadata order: x, pair_idx, W1, b1, g1, be1, m1, v1,
    //                 W2, b2, g2, be2, m2, v2, W3, b3, Wout, bout
    const float* x    = (const float*)d_in[0];
    // d_in[1] = pair_idx — intentionally unused (computed analytically on device)
    const float* W1   = (const float*)d_in[2];
    const float* b1   = (const float*)d_in[3];
    const float* g1   = (const float*)d_in[4];
    const float* be1  = (const float*)d_in[5];
    const float* m1   = (const float*)d_in[6];
    const float* v1   = (const float*)d_in[7];
    const float* W2   = (const float*)d_in[8];
    const float* b2   = (const float*)d_in[9];
    const float* g2   = (const float*)d_in[10];
    const float* be2  = (const float*)d_in[11];
    const float* m2   = (const float*)d_in[12];
    const float* v2   = (const float*)d_in[13];
    const float* W3   = (const float*)d_in[14];
    const float* b3   = (const float*)d_in[15];
    const float* Wout = (const float*)d_in[16];
    const float* bout = (const float*)d_in[17];
    float* out = (float*)d_out;

    dim3 grid(NMC, B / BT);   // (31, 16)
    nam_mma_kernel<<<grid, 256>>>(x, W1, b1, g1, be1, m1, v1,
                                  W2, b2, g2, be2, m2, v2, W3, b3,
                                  bout, out);
    dim3 grid2(B / 256, MSPLIT);
    nam_head_kernel<<<grid2, 256>>>(Wout, out);
}

// round 13
// speedup vs baseline: 1.4579x; 1.4579x over previous
#include <cuda_runtime.h>
#include <cuda_fp16.h>
#include <cstdint>

#define B    2048
#define NC   32
#define M    496
#define H1   64
#define H2   32
#define CLS  10
#define EPS  1e-5f
#define MPB  16                // modules per block
#define NMC  (M / MPB)         // 31 module-chunks
#define BT   128               // batch rows per block
#define MSPLIT 31
#define MCHUNK (M / MSPLIT)    // 16

// ---- smem word layout ----
// xs: 128 rows * 33 words = 4224 words
// two buffers, each 1444 words: BF[1056] | ABC[256] | DEW[128] | b3[1] | pad
#define XS_W    0
#define BUF0_W  4224
#define BUF1_W  5668
#define BUF_ABC 1056
#define BUF_DEW 1312
#define BUF_B3  1440
#define SMEM_W  7112

// Per-module outputs, transposed: g_ot[m*B + b]
__device__ float g_ot[M * B];

static __device__ __forceinline__ uint32_t f16x2(float hi, float lo) {
    uint32_t r;
    asm("cvt.rn.f16x2.f32 %0, %1, %2;" : "=r"(r) : "f"(hi), "f"(lo));
    return r;   // hi -> [31:16], lo -> [15:0]
}

static __device__ __forceinline__ void mma16816(float c[4],
    uint32_t a0, uint32_t a1, uint32_t a2, uint32_t a3,
    uint32_t b0, uint32_t b1)
{
    asm volatile(
        "mma.sync.aligned.m16n8k16.row.col.f32.f16.f16.f32 "
        "{%0,%1,%2,%3}, {%4,%5,%6,%7}, {%8,%9}, {%0,%1,%2,%3};"
        : "+f"(c[0]), "+f"(c[1]), "+f"(c[2]), "+f"(c[3])
        : "r"(a0), "r"(a1), "r"(a2), "r"(a3), "r"(b0), "r"(b1));
}

static __device__ __forceinline__ void adv_pair(int& i, int& j) {
    if (++j == NC) { ++i; j = i + 1; }
}

static __device__ __forceinline__ float relu_aff(float4 c, float xa, float xb) {
    return fmaxf(fmaf(c.x, xa, fmaf(c.y, xb, c.z)), 0.0f);
}

__global__ __launch_bounds__(256, 4) void nam_mma_kernel(
    const float* __restrict__ x,
    const float* __restrict__ W1, const float* __restrict__ b1,
    const float* __restrict__ g1, const float* __restrict__ be1,
    const float* __restrict__ m1, const float* __restrict__ v1,
    const float* __restrict__ W2, const float* __restrict__ b2,
    const float* __restrict__ g2, const float* __restrict__ be2,
    const float* __restrict__ m2, const float* __restrict__ v2,
    const float* __restrict__ W3, const float* __restrict__ b3,
    const float* __restrict__ bout,
    float* __restrict__ out)
{
    __shared__ __align__(16) uint32_t smw[SMEM_W];

    const int tid  = threadIdx.x;
    const int lane = tid & 31;
    const int w    = tid >> 5;          // warp 0..7 -> rows 16w..16w+15
    const int gid  = lane >> 2;         // 0..7
    const int tig  = lane & 3;          // 0..3
    const int yoff = blockIdx.y * BT;
    const int m0   = blockIdx.x * MPB;

    // Fold out-init into this kernel (out is poisoned by the harness).
    if (blockIdx.x == 0 && tid < BT) {
        #pragma unroll
        for (int c = 0; c < CLS; c++) out[(yoff + tid) * CLS + c] = bout[c];
    }

    // ---- stage x tile [128][32] padded to 33 words/row ----
    float* xs = (float*)smw;
    #pragma unroll
    for (int r = 0; r < (BT * NC) / 256; r++) {
        const int i = tid + r * 256;
        const int rr = i >> 5, cc = i & 31;
        xs[rr * 33 + cc] = x[(yoff + rr) * NC + cc];
    }

    // ---- staging roles ----
    const bool rABC = tid < H1;
    const bool rDEW = tid >= H1 && tid < H1 + H2;
    const bool rB3  = tid == H1 + H2;
    float2 pw[4];

    // pair indices for the module currently in the MMA phase
    int ci, cj;
    { int rem = m0, i = 0;
      while (rem >= NC - 1 - i) { rem -= NC - 1 - i; i++; }
      ci = i; cj = i + 1 + rem; }

    // commit helper (as a lambda-free macro-ish block below); prologue:
    // prefetch W2(m0), commit m0 -> buf0, prefetch W2(m1)
    {
        const float2* w2p = (const float2*)(W2 + m0 * (H2 * H1));
        #pragma unroll
        for (int r = 0; r < 4; r++) pw[r] = w2p[tid + r * 256];
    }

    #define COMMIT(BUFW, MN)                                                   \
    do {                                                                       \
        _Pragma("unroll")                                                      \
        for (int r = 0; r < 4; r++) {                                          \
            const int p  = tid + r * 256;                                      \
            const int o  = p >> 5;                                             \
            const int pk = p & 31;                                             \
            const int ks   = pk >> 3;                                          \
            const int wtig = pk & 3;                                           \
            const int slot = (pk >> 2) & 1;                                    \
            const int nt   = o >> 3;                                           \
            const int go   = o & 7;                                            \
            smw[(BUFW) + (ks*4 + nt)*66 + 8*go + 2*wtig + slot] =              \
                f16x2(pw[r].y, pw[r].x);                                       \
        }                                                                      \
        if (rABC) {                                                            \
            const int o = tid;                                                 \
            const float s = g1[(MN)*H1 + o] * rsqrtf(v1[(MN)*H1 + o] + EPS);   \
            ((float4*)(smw + (BUFW) + BUF_ABC))[o] = make_float4(              \
                s * W1[((MN)*H1 + o)*2], s * W1[((MN)*H1 + o)*2 + 1],          \
                s * (b1[(MN)*H1 + o] - m1[(MN)*H1 + o]) + be1[(MN)*H1 + o],    \
                0.0f);                                                         \
        } else if (rDEW) {                                                     \
            const int o = tid - H1;                                            \
            const float s = g2[(MN)*H2 + o] * rsqrtf(v2[(MN)*H2 + o] + EPS);   \
            ((float4*)(smw + (BUFW) + BUF_DEW))[o] = make_float4(              \
                s, s * (b2[(MN)*H2 + o] - m2[(MN)*H2 + o]) + be2[(MN)*H2 + o], \
                W3[(MN)*H2 + o], 0.0f);                                        \
        } else if (rB3) {                                                      \
            ((float*)(smw + (BUFW) + BUF_B3))[0] = b3[MN];                     \
        }                                                                      \
    } while (0)

    COMMIT(BUF0_W, m0);
    {
        const float2* w2p = (const float2*)(W2 + (m0 + 1) * (H2 * H1));
        #pragma unroll
        for (int r = 0; r < 4; r++) pw[r] = w2p[tid + r * 256];
    }
    __syncthreads();

    const int r0 = 16 * w + gid;      // this thread's fragment rows
    const int r1 = r0 + 8;
    int p = 0;

    for (int mi = 0; mi < MPB; mi++) {
        const uint32_t bufW  = p ? BUF1_W : BUF0_W;
        const uint32_t obufW = p ? BUF0_W : BUF1_W;

        // ---- commit module mi+1 into the other buffer, prefetch mi+2 ----
        if (mi + 1 < MPB) {
            COMMIT(obufW, m0 + mi + 1);
            if (mi + 2 < MPB) {
                const float2* w2p = (const float2*)(W2 + (m0 + mi + 2) * (H2 * H1));
                #pragma unroll
                for (int r = 0; r < 4; r++) pw[r] = w2p[tid + r * 256];
            }
        }

        // ---- layer1-in-fragments + MMA for module mi ----
        const float4* ABC = (const float4*)(smw + bufW + BUF_ABC);
        const float xa0 = xs[r0 * 33 + ci], xb0 = xs[r0 * 33 + cj];
        const float xa1 = xs[r1 * 33 + ci], xb1 = xs[r1 * 33 + cj];

        float cf[4][4];
        #pragma unroll
        for (int nt = 0; nt < 4; nt++)
            #pragma unroll
            for (int j = 0; j < 4; j++) cf[nt][j] = 0.0f;

        #pragma unroll
        for (int ks = 0; ks < 4; ks++) {
            const int k0 = 16 * ks + 2 * tig;
            const float4 cA = ABC[k0];
            const float4 cB = ABC[k0 + 1];
            const float4 cC = ABC[k0 + 8];
            const float4 cD = ABC[k0 + 9];
            const uint32_t a0 = f16x2(relu_aff(cB, xa0, xb0), relu_aff(cA, xa0, xb0));
            const uint32_t a1 = f16x2(relu_aff(cB, xa1, xb1), relu_aff(cA, xa1, xb1));
            const uint32_t a2 = f16x2(relu_aff(cD, xa0, xb0), relu_aff(cC, xa0, xb0));
            const uint32_t a3 = f16x2(relu_aff(cD, xa1, xb1), relu_aff(cC, xa1, xb1));
            uint2 bf[4];
            #pragma unroll
            for (int nt = 0; nt < 4; nt++)
                bf[nt] = *((const uint2*)(smw + bufW + (ks*4 + nt)*66 + lane*2));
            #pragma unroll
            for (int nt = 0; nt < 4; nt++)
                mma16816(cf[nt], a0, a1, a2, a3, bf[nt].x, bf[nt].y);
        }

        // ---- epilogue: BN2 + ReLU + W3, row-reduce, write g_ot ----
        const float4* DEW = (const float4*)(smw + bufW + BUF_DEW);
        float p0 = 0.0f, p1 = 0.0f;
        #pragma unroll
        for (int nt = 0; nt < 4; nt++) {
            const int n0 = 8*nt + 2*tig;
            const float4 d0 = DEW[n0];
            const float4 d1 = DEW[n0 + 1];
            p0 = fmaf(d0.z, fmaxf(fmaf(d0.x, cf[nt][0], d0.y), 0.0f), p0);
            p0 = fmaf(d1.z, fmaxf(fmaf(d1.x, cf[nt][1], d1.y), 0.0f), p0);
            p1 = fmaf(d0.z, fmaxf(fmaf(d0.x, cf[nt][2], d0.y), 0.0f), p1);
            p1 = fmaf(d1.z, fmaxf(fmaf(d1.x, cf[nt][3], d1.y), 0.0f), p1);
        }
        p0 += __shfl_xor_sync(0xffffffffu, p0, 1);
        p0 += __shfl_xor_sync(0xffffffffu, p0, 2);
        p1 += __shfl_xor_sync(0xffffffffu, p1, 1);
        p1 += __shfl_xor_sync(0xffffffffu, p1, 2);

        if (tig == 0) {
            const float b3s = ((const float*)(smw + bufW + BUF_B3))[0];
            g_ot[(m0 + mi) * B + yoff + r0] = b3s + p0;
            g_ot[(m0 + mi) * B + yoff + r1] = b3s + p1;
        }

        __syncthreads();   // next buffer committed; this buffer's reads done
        adv_pair(ci, cj);
        p ^= 1;
    }
    #undef COMMIT
}

// Head: grid (B/256, MSPLIT). Thread = one b; reads 16 g values once each,
// accumulates all 10 classes in registers, then 10 low-duplication atomics.
__global__ __launch_bounds__(256) void nam_head_kernel(
    const float* __restrict__ Wout,   // [CLS, M]
    float* __restrict__ out)          // [B, CLS]
{
    const int tid = threadIdx.x;
    const int b   = blockIdx.x * 256 + tid;
    const int m0  = blockIdx.y * MCHUNK;

    __shared__ float ws[MCHUNK * CLS];   // ws[j][c] = Wout[c][m0+j]
    if (tid < MCHUNK * CLS) {
        const int j = tid / CLS;
        const int c = tid % CLS;
        ws[tid] = Wout[c * M + m0 + j];
    }
    __syncthreads();

    float acc[CLS];
    #pragma unroll
    for (int c = 0; c < CLS; c++) acc[c] = 0.0f;

    const float* __restrict__ gcol = g_ot + m0 * B + b;
    #pragma unroll
    for (int j = 0; j < MCHUNK; j++) {
        const float g = gcol[j * B];             // coalesced LDG
        #pragma unroll
        for (int c = 0; c < CLS; c++)
            acc[c] = fmaf(g, ws[j * CLS + c], acc[c]);   // smem broadcast
    }

    #pragma unroll
    for (int c = 0; c < CLS; c++)
        atomicAdd(&out[b * CLS + c], acc[c]);
}

extern "C" void kernel_launch(void* const* d_in, const int* in_sizes, int n_in,
                              void* d_out, int out_size)
{
    // metadata order: x, pair_idx, W1, b1, g1, be1, m1, v1,
    //                 W2, b2, g2, be2, m2, v2, W3, b3, Wout, bout
    const float* x    = (const float*)d_in[0];
    // d_in[1] = pair_idx — intentionally unused (computed analytically on device)
    const float* W1   = (const float*)d_in[2];
    const float* b1   = (const float*)d_in[3];
    const float* g1   = (const float*)d_in[4];
    const float* be1  = (const float*)d_in[5];
    const float* m1   = (const float*)d_in[6];
    const float* v1   = (const float*)d_in[7];
    const float* W2   = (const float*)d_in[8];
    const float* b2   = (const float*)d_in[9];
    const float* g2   = (const float*)d_in[10];
    const float* be2  = (const float*)d_in[11];
    const float* m2   = (const float*)d_in[12];
    const float* v2   = (const float*)d_in[13];
    const float* W3   = (const float*)d_in[14];
    const float* b3   = (const float*)d_in[15];
    const float* Wout = (const float*)d_in[16];
    const float* bout = (const float*)d_in[17];
    float* out = (float*)d_out;

    dim3 grid(NMC, B / BT);   // (31, 16)
    nam_mma_kernel<<<grid, 256>>>(x, W1, b1, g1, be1, m1, v1,
                                  W2, b2, g2, be2, m2, v2, W3, b3,
                                  bout, out);
    dim3 grid2(B / 256, MSPLIT);
    nam_head_kernel<<<grid2, 256>>>(Wout, out);
}

// round 14
// speedup vs baseline: 1.5069x; 1.0336x over previous
#include <cuda_runtime.h>
#include <cuda_fp16.h>
#include <cstdint>

#define B    2048
#define NC   32
#define M    496
#define H1   64
#define H2   32
#define CLS  10
#define EPS  1e-5f
#define MPB  16                // modules per block
#define NMC  (M / MPB)         // 31 module-chunks
#define BT   128               // batch rows per block

// ---- smem word layout ----
// xs: 128 rows * 33 words = 4224 words
// two buffers, each 1444 words: BF[1056] | ABC[256] | DEW[128] | b3[1] | pad
// resbuf: 16 * 128 words; wouts: 160 words
#define XS_W    0
#define BUF0_W  4224
#define BUF1_W  5668
#define BUF_ABC 1056
#define BUF_DEW 1312
#define BUF_B3  1440
#define RES_W   7112
#define WOUTS_W 9160
#define SMEM_W  9320           // 37280 bytes

// Head partials: g_part[chunk][b][c] (unique writer per element -> no atomics)
__device__ float g_part[NMC * B * CLS];

static __device__ __forceinline__ uint32_t f16x2(float hi, float lo) {
    uint32_t r;
    asm("cvt.rn.f16x2.f32 %0, %1, %2;" : "=r"(r) : "f"(hi), "f"(lo));
    return r;   // hi -> [31:16], lo -> [15:0]
}

static __device__ __forceinline__ void mma16816(float c[4],
    uint32_t a0, uint32_t a1, uint32_t a2, uint32_t a3,
    uint32_t b0, uint32_t b1)
{
    asm volatile(
        "mma.sync.aligned.m16n8k16.row.col.f32.f16.f16.f32 "
        "{%0,%1,%2,%3}, {%4,%5,%6,%7}, {%8,%9}, {%0,%1,%2,%3};"
        : "+f"(c[0]), "+f"(c[1]), "+f"(c[2]), "+f"(c[3])
        : "r"(a0), "r"(a1), "r"(a2), "r"(a3), "r"(b0), "r"(b1));
}

static __device__ __forceinline__ void adv_pair(int& i, int& j) {
    if (++j == NC) { ++i; j = i + 1; }
}

static __device__ __forceinline__ float relu_aff(float4 c, float xa, float xb) {
    return fmaxf(fmaf(c.x, xa, fmaf(c.y, xb, c.z)), 0.0f);
}

__global__ __launch_bounds__(256, 4) void nam_mma_kernel(
    const float* __restrict__ x,
    const float* __restrict__ W1, const float* __restrict__ b1,
    const float* __restrict__ g1, const float* __restrict__ be1,
    const float* __restrict__ m1, const float* __restrict__ v1,
    const float* __restrict__ W2, const float* __restrict__ b2,
    const float* __restrict__ g2, const float* __restrict__ be2,
    const float* __restrict__ m2, const float* __restrict__ v2,
    const float* __restrict__ W3, const float* __restrict__ b3,
    const float* __restrict__ Wout)
{
    __shared__ __align__(16) uint32_t smw[SMEM_W];

    const int tid  = threadIdx.x;
    const int lane = tid & 31;
    const int w    = tid >> 5;          // warp 0..7 -> rows 16w..16w+15
    const int gid  = lane >> 2;         // 0..7
    const int tig  = lane & 3;          // 0..3
    const int yoff = blockIdx.y * BT;
    const int m0   = blockIdx.x * MPB;

    // ---- stage x tile [128][32] padded to 33 words/row ----
    float* xs = (float*)smw;
    #pragma unroll
    for (int r = 0; r < (BT * NC) / 256; r++) {
        const int i = tid + r * 256;
        const int rr = i >> 5, cc = i & 31;
        xs[rr * 33 + cc] = x[(yoff + rr) * NC + cc];
    }

    // ---- stage wouts[mi][c] = Wout[c][m0+mi] (used only in the tail) ----
    if (tid < MPB * CLS) {
        const int mi2 = tid / CLS, c = tid % CLS;
        ((float*)(smw + WOUTS_W))[tid] = Wout[c * M + m0 + mi2];
    }

    // ---- staging roles ----
    const bool rABC = tid < H1;
    const bool rDEW = tid >= H1 && tid < H1 + H2;
    const bool rB3  = tid == H1 + H2;
    float2 pw[4];

    // pair indices for the module currently in the MMA phase
    int ci, cj;
    { int rem = m0, i = 0;
      while (rem >= NC - 1 - i) { rem -= NC - 1 - i; i++; }
      ci = i; cj = i + 1 + rem; }

    {
        const float2* w2p = (const float2*)(W2 + m0 * (H2 * H1));
        #pragma unroll
        for (int r = 0; r < 4; r++) pw[r] = w2p[tid + r * 256];
    }

    #define COMMIT(BUFW, MN)                                                   \
    do {                                                                       \
        _Pragma("unroll")                                                      \
        for (int r = 0; r < 4; r++) {                                          \
            const int p  = tid + r * 256;                                      \
            const int o  = p >> 5;                                             \
            const int pk = p & 31;                                             \
            const int ks   = pk >> 3;                                          \
            const int wtig = pk & 3;                                           \
            const int slot = (pk >> 2) & 1;                                    \
            const int nt   = o >> 3;                                           \
            const int go   = o & 7;                                            \
            smw[(BUFW) + (ks*4 + nt)*66 + 8*go + 2*wtig + slot] =              \
                f16x2(pw[r].y, pw[r].x);                                       \
        }                                                                      \
        if (rABC) {                                                            \
            const int o = tid;                                                 \
            const float s = g1[(MN)*H1 + o] * rsqrtf(v1[(MN)*H1 + o] + EPS);   \
            ((float4*)(smw + (BUFW) + BUF_ABC))[o] = make_float4(              \
                s * W1[((MN)*H1 + o)*2], s * W1[((MN)*H1 + o)*2 + 1],          \
                s * (b1[(MN)*H1 + o] - m1[(MN)*H1 + o]) + be1[(MN)*H1 + o],    \
                0.0f);                                                         \
        } else if (rDEW) {                                                     \
            const int o = tid - H1;                                            \
            const float s = g2[(MN)*H2 + o] * rsqrtf(v2[(MN)*H2 + o] + EPS);   \
            ((float4*)(smw + (BUFW) + BUF_DEW))[o] = make_float4(              \
                s, s * (b2[(MN)*H2 + o] - m2[(MN)*H2 + o]) + be2[(MN)*H2 + o], \
                W3[(MN)*H2 + o], 0.0f);                                        \
        } else if (rB3) {                                                      \
            ((float*)(smw + (BUFW) + BUF_B3))[0] = b3[MN];                     \
        }                                                                      \
    } while (0)

    COMMIT(BUF0_W, m0);
    {
        const float2* w2p = (const float2*)(W2 + (m0 + 1) * (H2 * H1));
        #pragma unroll
        for (int r = 0; r < 4; r++) pw[r] = w2p[tid + r * 256];
    }
    __syncthreads();

    const int r0 = 16 * w + gid;      // this thread's fragment rows
    const int r1 = r0 + 8;
    float* resb = (float*)(smw + RES_W);
    int p = 0;

    for (int mi = 0; mi < MPB; mi++) {
        const uint32_t bufW  = p ? BUF1_W : BUF0_W;
        const uint32_t obufW = p ? BUF0_W : BUF1_W;

        // ---- commit module mi+1 into the other buffer, prefetch mi+2 ----
        if (mi + 1 < MPB) {
            COMMIT(obufW, m0 + mi + 1);
            if (mi + 2 < MPB) {
                const float2* w2p = (const float2*)(W2 + (m0 + mi + 2) * (H2 * H1));
                #pragma unroll
                for (int r = 0; r < 4; r++) pw[r] = w2p[tid + r * 256];
            }
        }

        // ---- layer1-in-fragments + MMA for module mi ----
        const float4* ABC = (const float4*)(smw + bufW + BUF_ABC);
        const float xa0 = xs[r0 * 33 + ci], xb0 = xs[r0 * 33 + cj];
        const float xa1 = xs[r1 * 33 + ci], xb1 = xs[r1 * 33 + cj];

        float cf[4][4];
        #pragma unroll
        for (int nt = 0; nt < 4; nt++)
            #pragma unroll
            for (int j = 0; j < 4; j++) cf[nt][j] = 0.0f;

        #pragma unroll
        for (int ks = 0; ks < 4; ks++) {
            const int k0 = 16 * ks + 2 * tig;
            const float4 cA = ABC[k0];
            const float4 cB = ABC[k0 + 1];
            const float4 cC = ABC[k0 + 8];
            const float4 cD = ABC[k0 + 9];
            const uint32_t a0 = f16x2(relu_aff(cB, xa0, xb0), relu_aff(cA, xa0, xb0));
            const uint32_t a1 = f16x2(relu_aff(cB, xa1, xb1), relu_aff(cA, xa1, xb1));
            const uint32_t a2 = f16x2(relu_aff(cD, xa0, xb0), relu_aff(cC, xa0, xb0));
            const uint32_t a3 = f16x2(relu_aff(cD, xa1, xb1), relu_aff(cC, xa1, xb1));
            uint2 bf[4];
            #pragma unroll
            for (int nt = 0; nt < 4; nt++)
                bf[nt] = *((const uint2*)(smw + bufW + (ks*4 + nt)*66 + lane*2));
            #pragma unroll
            for (int nt = 0; nt < 4; nt++)
                mma16816(cf[nt], a0, a1, a2, a3, bf[nt].x, bf[nt].y);
        }

        // ---- epilogue: BN2 + ReLU + W3, row-reduce, stash res in smem ----
        const float4* DEW = (const float4*)(smw + bufW + BUF_DEW);
        float p0 = 0.0f, p1 = 0.0f;
        #pragma unroll
        for (int nt = 0; nt < 4; nt++) {
            const int n0 = 8*nt + 2*tig;
            const float4 d0 = DEW[n0];
            const float4 d1 = DEW[n0 + 1];
            p0 = fmaf(d0.z, fmaxf(fmaf(d0.x, cf[nt][0], d0.y), 0.0f), p0);
            p0 = fmaf(d1.z, fmaxf(fmaf(d1.x, cf[nt][1], d1.y), 0.0f), p0);
            p1 = fmaf(d0.z, fmaxf(fmaf(d0.x, cf[nt][2], d0.y), 0.0f), p1);
            p1 = fmaf(d1.z, fmaxf(fmaf(d1.x, cf[nt][3], d1.y), 0.0f), p1);
        }
        p0 += __shfl_xor_sync(0xffffffffu, p0, 1);
        p0 += __shfl_xor_sync(0xffffffffu, p0, 2);
        p1 += __shfl_xor_sync(0xffffffffu, p1, 1);
        p1 += __shfl_xor_sync(0xffffffffu, p1, 2);

        if (tig == 0) {
            const float b3s = ((const float*)(smw + bufW + BUF_B3))[0];
            resb[mi * BT + r0] = b3s + p0;
            resb[mi * BT + r1] = b3s + p1;
        }

        __syncthreads();   // next buffer committed; resbuf/this buffer ordered
        adv_pair(ci, cj);
        p ^= 1;
    }
    #undef COMMIT

    // ---- in-block head tail: 256 threads = (row, c-half) ----
    {
        const int row = tid & 127;
        const int c0  = (tid >> 7) * 5;           // 0 or 5
        const float* wo = (const float*)(smw + WOUTS_W);
        float acc[5] = {0.0f, 0.0f, 0.0f, 0.0f, 0.0f};
        #pragma unroll
        for (int mi2 = 0; mi2 < MPB; mi2++) {
            const float g = resb[mi2 * BT + row];
            #pragma unroll
            for (int c = 0; c < 5; c++)
                acc[c] = fmaf(g, wo[mi2 * CLS + c0 + c], acc[c]);
        }
        float* dst = g_part + ((size_t)blockIdx.x * B + yoff + row) * CLS + c0;
        #pragma unroll
        for (int c = 0; c < 5; c++) dst[c] = acc[c];
    }
}

// out[i] = bout[i%CLS] + sum_chunks g_part[mc][i]; one thread per element.
__global__ __launch_bounds__(256) void nam_reduce_kernel(
    const float* __restrict__ bout, float* __restrict__ out)
{
    const int i = blockIdx.x * 256 + threadIdx.x;
    if (i >= B * CLS) return;
    float s = bout[i % CLS];
    #pragma unroll
    for (int mc = 0; mc < NMC; mc++)
        s += g_part[mc * (B * CLS) + i];
    out[i] = s;
}

extern "C" void kernel_launch(void* const* d_in, const int* in_sizes, int n_in,
                              void* d_out, int out_size)
{
    // metadata order: x, pair_idx, W1, b1, g1, be1, m1, v1,
    //                 W2, b2, g2, be2, m2, v2, W3, b3, Wout, bout
    const float* x    = (const float*)d_in[0];
    // d_in[1] = pair_idx — intentionally unused (computed analytically on device)
    const float* W1   = (const float*)d_in[2];
    const float* b1   = (const float*)d_in[3];
    const float* g1   = (const float*)d_in[4];
    const float* be1  = (const float*)d_in[5];
    const float* m1   = (const float*)d_in[6];
    const float* v1   = (const float*)d_in[7];
    const float* W2   = (const float*)d_in[8];
    const float* b2   = (const float*)d_in[9];
    const float* g2   = (const float*)d_in[10];
    const float* be2  = (const float*)d_in[11];
    const float* m2   = (const float*)d_in[12];
    const float* v2   = (const float*)d_in[13];
    const float* W3   = (const float*)d_in[14];
    const float* b3   = (const float*)d_in[15];
    const float* Wout = (const float*)d_in[16];
    const float* bout = (const float*)d_in[17];
    float* out = (float*)d_out;

    dim3 grid(NMC, B / BT);   // (31, 16)
    nam_mma_kernel<<<grid, 256>>>(x, W1, b1, g1, be1, m1, v1,
                                  W2, b2, g2, be2, m2, v2, W3, b3, Wout);
    nam_reduce_kernel<<<(B * CLS + 255) / 256, 256>>>(bout, out);
}

// round 15
// speedup vs baseline: 1.5136x; 1.0044x over previous
#include <cuda_runtime.h>
#include <cuda_fp16.h>
#include <cstdint>

#define B    2048
#define NC   32
#define M    496
#define H1   64
#define H2   32
#define CLS  10
#define EPS  1e-5f
#define MPB  16                // modules per block
#define NMC  (M / MPB)         // 31 module-chunks
#define BT   128               // batch rows per block

// ---- per-module blob layout (words): BF[1056] ABC[256] DEW[128] b3[1] pad ----
#define BLOB_ABC 1056
#define BLOB_DEW 1312
#define BLOB_B3  1440
#define BLOB_W   1456          // 5824 B = 364 x 16B

// ---- smem word layout ----
#define XS_W    0              // 128 rows * 33 words
#define BUF0_W  4224
#define BUF1_W  (BUF0_W + BLOB_W)   // 5680
#define RES_W   (BUF1_W + BLOB_W)   // 7136
#define WOUTS_W (RES_W + MPB * BT)  // 9184
#define SMEM_W  (WOUTS_W + MPB * CLS)  // 9344 words = 37376 B

// Pre-folded per-module weight blobs (written by prep_kernel each launch)
__device__ uint32_t g_blob[(size_t)M * BLOB_W];
// Head partials: g_part[chunk][b][c] (unique writer per element -> no atomics)
__device__ float g_part[NMC * B * CLS];

static __device__ __forceinline__ uint32_t f16x2(float hi, float lo) {
    uint32_t r;
    asm("cvt.rn.f16x2.f32 %0, %1, %2;" : "=r"(r) : "f"(hi), "f"(lo));
    return r;   // hi -> [31:16], lo -> [15:0]
}

static __device__ __forceinline__ uint32_t smem_u32(const void* p) {
    uint32_t a;
    asm("{ .reg .u64 t; cvta.to.shared.u64 t, %1; cvt.u32.u64 %0, t; }"
        : "=r"(a) : "l"(p));
    return a;
}

static __device__ __forceinline__ void mma16816(float c[4],
    uint32_t a0, uint32_t a1, uint32_t a2, uint32_t a3,
    uint32_t b0, uint32_t b1)
{
    asm volatile(
        "mma.sync.aligned.m16n8k16.row.col.f32.f16.f16.f32 "
        "{%0,%1,%2,%3}, {%4,%5,%6,%7}, {%8,%9}, {%0,%1,%2,%3};"
        : "+f"(c[0]), "+f"(c[1]), "+f"(c[2]), "+f"(c[3])
        : "r"(a0), "r"(a1), "r"(a2), "r"(a3), "r"(b0), "r"(b1));
}

static __device__ __forceinline__ void adv_pair(int& i, int& j) {
    if (++j == NC) { ++i; j = i + 1; }
}

static __device__ __forceinline__ float relu_aff(float4 c, float xa, float xb) {
    return fmaxf(fmaf(c.x, xa, fmaf(c.y, xb, c.z)), 0.0f);
}

// Async-copy one module blob (364 x 16B) into a smem buffer.
static __device__ __forceinline__ void cpa_blob(uint32_t sdst, const uint32_t* src,
                                                int tid) {
    {
        asm volatile("cp.async.ca.shared.global [%0], [%1], 16;"
                     :: "r"(sdst + tid * 16), "l"(src + tid * 4) : "memory");
        const int i2 = tid + 256;
        if (i2 < 364)
            asm volatile("cp.async.ca.shared.global [%0], [%1], 16;"
                         :: "r"(sdst + i2 * 16), "l"(src + i2 * 4) : "memory");
    }
    asm volatile("cp.async.commit_group;" ::: "memory");
}

// ---- prep: fold BN + convert W2 to fp16 fragment layout, once per module ----
__global__ __launch_bounds__(256) void prep_kernel(
    const float* __restrict__ W1, const float* __restrict__ b1,
    const float* __restrict__ g1, const float* __restrict__ be1,
    const float* __restrict__ m1, const float* __restrict__ v1,
    const float* __restrict__ W2, const float* __restrict__ b2,
    const float* __restrict__ g2, const float* __restrict__ be2,
    const float* __restrict__ m2, const float* __restrict__ v2,
    const float* __restrict__ W3, const float* __restrict__ b3)
{
    const int m   = blockIdx.x;
    const int tid = threadIdx.x;
    uint32_t* blob = g_blob + (size_t)m * BLOB_W;

    const float2* w2p = (const float2*)(W2 + m * (H2 * H1));
    #pragma unroll
    for (int r = 0; r < 4; r++) {
        const int p  = tid + r * 256;
        const int o  = p >> 5;
        const int pk = p & 31;
        const int ks   = pk >> 3;
        const int wtig = pk & 3;
        const int slot = (pk >> 2) & 1;
        const int nt   = o >> 3;
        const int go   = o & 7;
        const float2 wv = w2p[p];
        blob[(ks*4 + nt)*66 + 8*go + 2*wtig + slot] = f16x2(wv.y, wv.x);
    }
    if (tid < H1) {
        const int o = tid;
        const float s = g1[m*H1 + o] * rsqrtf(v1[m*H1 + o] + EPS);
        ((float4*)(blob + BLOB_ABC))[o] = make_float4(
            s * W1[(m*H1 + o)*2], s * W1[(m*H1 + o)*2 + 1],
            s * (b1[m*H1 + o] - m1[m*H1 + o]) + be1[m*H1 + o], 0.0f);
    } else if (tid < H1 + H2) {
        const int o = tid - H1;
        const float s = g2[m*H2 + o] * rsqrtf(v2[m*H2 + o] + EPS);
        ((float4*)(blob + BLOB_DEW))[o] = make_float4(
            s, s * (b2[m*H2 + o] - m2[m*H2 + o]) + be2[m*H2 + o],
            W3[m*H2 + o], 0.0f);
    } else if (tid == H1 + H2) {
        ((float*)(blob + BLOB_B3))[0] = b3[m];
    }
}

__global__ __launch_bounds__(256, 4) void nam_mma_kernel(
    const float* __restrict__ x,
    const float* __restrict__ Wout)
{
    __shared__ __align__(16) uint32_t smw[SMEM_W];

    const int tid  = threadIdx.x;
    const int lane = tid & 31;
    const int w    = tid >> 5;          // warp 0..7 -> rows 16w..16w+15
    const int gid  = lane >> 2;         // 0..7
    const int tig  = lane & 3;          // 0..3
    const int yoff = blockIdx.y * BT;
    const int m0   = blockIdx.x * MPB;
    const uint32_t sbase = smem_u32(smw);

    // ---- stage x tile [128][32] padded to 33 words/row ----
    float* xs = (float*)smw;
    #pragma unroll
    for (int r = 0; r < (BT * NC) / 256; r++) {
        const int i = tid + r * 256;
        const int rr = i >> 5, cc = i & 31;
        xs[rr * 33 + cc] = x[(yoff + rr) * NC + cc];
    }

    // ---- stage wouts[mi][c] = Wout[c][m0+mi] (used only in the tail) ----
    if (tid < MPB * CLS) {
        const int mi2 = tid / CLS, c = tid % CLS;
        ((float*)(smw + WOUTS_W))[tid] = Wout[c * M + m0 + mi2];
    }

    // pair indices for the module currently in the MMA phase
    int ci, cj;
    { int rem = m0, i = 0;
      while (rem >= NC - 1 - i) { rem -= NC - 1 - i; i++; }
      ci = i; cj = i + 1 + rem; }

    // ---- prologue: async-load blobs for m0, m0+1 ----
    cpa_blob(sbase + BUF0_W * 4, g_blob + (size_t)m0 * BLOB_W, tid);
    cpa_blob(sbase + BUF1_W * 4, g_blob + (size_t)(m0 + 1) * BLOB_W, tid);
    asm volatile("cp.async.wait_group 1;" ::: "memory");   // m0 landed
    __syncthreads();

    const int r0 = 16 * w + gid;      // this thread's fragment rows
    const int r1 = r0 + 8;
    float* resb = (float*)(smw + RES_W);
    int p = 0;

    for (int mi = 0; mi < MPB; mi++) {
        const uint32_t bufW = p ? BUF1_W : BUF0_W;

        // ---- layer1-in-fragments + MMA for module mi ----
        const float4* ABC = (const float4*)(smw + bufW + BLOB_ABC);
        const float xa0 = xs[r0 * 33 + ci], xb0 = xs[r0 * 33 + cj];
        const float xa1 = xs[r1 * 33 + ci], xb1 = xs[r1 * 33 + cj];

        float cf[4][4];
        #pragma unroll
        for (int nt = 0; nt < 4; nt++)
            #pragma unroll
            for (int j = 0; j < 4; j++) cf[nt][j] = 0.0f;

        #pragma unroll
        for (int ks = 0; ks < 4; ks++) {
            const int k0 = 16 * ks + 2 * tig;
            const float4 cA = ABC[k0];
            const float4 cB = ABC[k0 + 1];
            const float4 cC = ABC[k0 + 8];
            const float4 cD = ABC[k0 + 9];
            const uint32_t a0 = f16x2(relu_aff(cB, xa0, xb0), relu_aff(cA, xa0, xb0));
            const uint32_t a1 = f16x2(relu_aff(cB, xa1, xb1), relu_aff(cA, xa1, xb1));
            const uint32_t a2 = f16x2(relu_aff(cD, xa0, xb0), relu_aff(cC, xa0, xb0));
            const uint32_t a3 = f16x2(relu_aff(cD, xa1, xb1), relu_aff(cC, xa1, xb1));
            uint2 bf[4];
            #pragma unroll
            for (int nt = 0; nt < 4; nt++)
                bf[nt] = *((const uint2*)(smw + bufW + (ks*4 + nt)*66 + lane*2));
            #pragma unroll
            for (int nt = 0; nt < 4; nt++)
                mma16816(cf[nt], a0, a1, a2, a3, bf[nt].x, bf[nt].y);
        }

        // ---- epilogue: BN2 + ReLU + W3, row-reduce, stash res in smem ----
        const float4* DEW = (const float4*)(smw + bufW + BLOB_DEW);
        float p0 = 0.0f, p1 = 0.0f;
        #pragma unroll
        for (int nt = 0; nt < 4; nt++) {
            const int n0 = 8*nt + 2*tig;
            const float4 d0 = DEW[n0];
            const float4 d1 = DEW[n0 + 1];
            p0 = fmaf(d0.z, fmaxf(fmaf(d0.x, cf[nt][0], d0.y), 0.0f), p0);
            p0 = fmaf(d1.z, fmaxf(fmaf(d1.x, cf[nt][1], d1.y), 0.0f), p0);
            p1 = fmaf(d0.z, fmaxf(fmaf(d0.x, cf[nt][2], d0.y), 0.0f), p1);
            p1 = fmaf(d1.z, fmaxf(fmaf(d1.x, cf[nt][3], d1.y), 0.0f), p1);
        }
        p0 += __shfl_xor_sync(0xffffffffu, p0, 1);
        p0 += __shfl_xor_sync(0xffffffffu, p0, 2);
        p1 += __shfl_xor_sync(0xffffffffu, p1, 1);
        p1 += __shfl_xor_sync(0xffffffffu, p1, 2);

        if (tig == 0) {
            const float b3s = ((const float*)(smw + bufW + BLOB_B3))[0];
            resb[mi * BT + r0] = b3s + p0;
            resb[mi * BT + r1] = b3s + p1;
        }

        // copy of module mi+1 must be complete everywhere before next iter
        asm volatile("cp.async.wait_group 0;" ::: "memory");
        __syncthreads();
        // refill the buffer just consumed with module mi+2
        if (mi + 2 < MPB)
            cpa_blob(sbase + bufW * 4, g_blob + (size_t)(m0 + mi + 2) * BLOB_W, tid);

        adv_pair(ci, cj);
        p ^= 1;
    }

    // ---- in-block head tail: 256 threads = (row, c-half) ----
    {
        const int row = tid & 127;
        const int c0  = (tid >> 7) * 5;           // 0 or 5
        const float* wo = (const float*)(smw + WOUTS_W);
        float acc[5] = {0.0f, 0.0f, 0.0f, 0.0f, 0.0f};
        #pragma unroll
        for (int mi2 = 0; mi2 < MPB; mi2++) {
            const float g = resb[mi2 * BT + row];
            #pragma unroll
            for (int c = 0; c < 5; c++)
                acc[c] = fmaf(g, wo[mi2 * CLS + c0 + c], acc[c]);
        }
        float* dst = g_part + ((size_t)blockIdx.x * B + yoff + row) * CLS + c0;
        #pragma unroll
        for (int c = 0; c < 5; c++) dst[c] = acc[c];
    }
}

// out[i] = bout[i%CLS] + sum_chunks g_part[mc][i]; one thread per element.
__global__ __launch_bounds__(256) void nam_reduce_kernel(
    const float* __restrict__ bout, float* __restrict__ out)
{
    const int i = blockIdx.x * 256 + threadIdx.x;
    if (i >= B * CLS) return;
    float s = bout[i % CLS];
    #pragma unroll
    for (int mc = 0; mc < NMC; mc++)
        s += g_part[mc * (B * CLS) + i];
    out[i] = s;
}

extern "C" void kernel_launch(void* const* d_in, const int* in_sizes, int n_in,
                              void* d_out, int out_size)
{
    // metadata order: x, pair_idx, W1, b1, g1, be1, m1, v1,
    //                 W2, b2, g2, be2, m2, v2, W3, b3, Wout, bout
    const float* x    = (const float*)d_in[0];
    // d_in[1] = pair_idx — intentionally unused (computed analytically on device)
    const float* W1   = (const float*)d_in[2];
    const float* b1   = (const float*)d_in[3];
    const float* g1   = (const float*)d_in[4];
    const float* be1  = (const float*)d_in[5];
    const float* m1   = (const float*)d_in[6];
    const float* v1   = (const float*)d_in[7];
    const float* W2   = (const float*)d_in[8];
    const float* b2   = (const float*)d_in[9];
    const float* g2   = (const float*)d_in[10];
    const float* be2  = (const float*)d_in[11];
    const float* m2   = (const float*)d_in[12];
    const float* v2   = (const float*)d_in[13];
    const float* W3   = (const float*)d_in[14];
    const float* b3   = (const float*)d_in[15];
    const float* Wout = (const float*)d_in[16];
    const float* bout = (const float*)d_in[17];
    float* out = (float*)d_out;

    prep_kernel<<<M, 256>>>(W1, b1, g1, be1, m1, v1,
                            W2, b2, g2, be2, m2, v2, W3, b3);
    dim3 grid(NMC, B / BT);   // (31, 16)
    nam_mma_kernel<<<grid, 256>>>(x, Wout);
    nam_reduce_kernel<<<(B * CLS + 255) / 256, 256>>>(bout, out);
}

// round 16
// speedup vs baseline: 1.5746x; 1.0403x over previous
#include <cuda_runtime.h>
#include <cuda_fp16.h>
#include <cstdint>

#define B    2048
#define NC   32
#define M    496
#define H1   64
#define H2   32
#define CLS  10
#define EPS  1e-5f
#define MPB  16                // modules per block
#define NMC  (M / MPB)         // 31 module-chunks
#define BT   128               // batch rows per block

// ---- per-module blob layout (words): BF[1056] ABC[256] DEW[128] b3[1] pad ----
#define BLOB_ABC 1056
#define BLOB_DEW 1312
#define BLOB_B3  1440
#define BLOB_W   1456          // 5824 B = 364 x 16B

// ---- smem word layout (4-slot blob ring) ----
#define XS_W    0                         // 128 rows * 33 words = 4224
#define BUF_W(i) (4224 + (i) * BLOB_W)    // 4 blob slots
#define RES_W   (4224 + 4 * BLOB_W)       // 10048: 16*128 res values
#define WOUTS_W (RES_W + MPB * BT)        // 12096
#define SMEM_W  (WOUTS_W + MPB * CLS)     // 12256 words = 49024 B (< 48KB)

// Pre-folded per-module weight blobs (written by prep_kernel each launch)
__device__ uint32_t g_blob[(size_t)M * BLOB_W];

static __device__ __forceinline__ uint32_t f16x2(float hi, float lo) {
    uint32_t r;
    asm("cvt.rn.f16x2.f32 %0, %1, %2;" : "=r"(r) : "f"(hi), "f"(lo));
    return r;   // hi -> [31:16], lo -> [15:0]
}

static __device__ __forceinline__ uint32_t smem_u32(const void* p) {
    uint32_t a;
    asm("{ .reg .u64 t; cvta.to.shared.u64 t, %1; cvt.u32.u64 %0, t; }"
        : "=r"(a) : "l"(p));
    return a;
}

static __device__ __forceinline__ void mma16816(float c[4],
    uint32_t a0, uint32_t a1, uint32_t a2, uint32_t a3,
    uint32_t b0, uint32_t b1)
{
    asm volatile(
        "mma.sync.aligned.m16n8k16.row.col.f32.f16.f16.f32 "
        "{%0,%1,%2,%3}, {%4,%5,%6,%7}, {%8,%9}, {%0,%1,%2,%3};"
        : "+f"(c[0]), "+f"(c[1]), "+f"(c[2]), "+f"(c[3])
        : "r"(a0), "r"(a1), "r"(a2), "r"(a3), "r"(b0), "r"(b1));
}

static __device__ __forceinline__ void adv_pair(int& i, int& j) {
    if (++j == NC) { ++i; j = i + 1; }
}

static __device__ __forceinline__ float relu_aff(float4 c, float xa, float xb) {
    return fmaxf(fmaf(c.x, xa, fmaf(c.y, xb, c.z)), 0.0f);
}

// Async-copy one module blob (364 x 16B) into a smem slot; one commit group.
static __device__ __forceinline__ void cpa_blob(uint32_t sdst, const uint32_t* src,
                                                int tid) {
    asm volatile("cp.async.ca.shared.global [%0], [%1], 16;"
                 :: "r"(sdst + tid * 16), "l"(src + tid * 4) : "memory");
    const int i2 = tid + 256;
    if (i2 < 364)
        asm volatile("cp.async.ca.shared.global [%0], [%1], 16;"
                     :: "r"(sdst + i2 * 16), "l"(src + i2 * 4) : "memory");
    asm volatile("cp.async.commit_group;" ::: "memory");
}

// ---- prep: fold BN + convert W2 to fp16 fragment layout + init out ----
__global__ __launch_bounds__(256) void prep_kernel(
    const float* __restrict__ W1, const float* __restrict__ b1,
    const float* __restrict__ g1, const float* __restrict__ be1,
    const float* __restrict__ m1, const float* __restrict__ v1,
    const float* __restrict__ W2, const float* __restrict__ b2,
    const float* __restrict__ g2, const float* __restrict__ be2,
    const float* __restrict__ m2, const float* __restrict__ v2,
    const float* __restrict__ W3, const float* __restrict__ b3,
    const float* __restrict__ bout, float* __restrict__ out)
{
    const int m   = blockIdx.x;
    const int tid = threadIdx.x;
    uint32_t* blob = g_blob + (size_t)m * BLOB_W;

    // init out[b][c] = bout[c] (out is poisoned by the harness)
    const int gi = blockIdx.x * 256 + tid;
    if (gi < B * CLS) out[gi] = bout[gi % CLS];

    const float2* w2p = (const float2*)(W2 + m * (H2 * H1));
    #pragma unroll
    for (int r = 0; r < 4; r++) {
        const int p  = tid + r * 256;
        const int o  = p >> 5;
        const int pk = p & 31;
        const int ks   = pk >> 3;
        const int wtig = pk & 3;
        const int slot = (pk >> 2) & 1;
        const int nt   = o >> 3;
        const int go   = o & 7;
        const float2 wv = w2p[p];
        blob[(ks*4 + nt)*66 + 8*go + 2*wtig + slot] = f16x2(wv.y, wv.x);
    }
    if (tid < H1) {
        const int o = tid;
        const float s = g1[m*H1 + o] * rsqrtf(v1[m*H1 + o] + EPS);
        ((float4*)(blob + BLOB_ABC))[o] = make_float4(
            s * W1[(m*H1 + o)*2], s * W1[(m*H1 + o)*2 + 1],
            s * (b1[m*H1 + o] - m1[m*H1 + o]) + be1[m*H1 + o], 0.0f);
    } else if (tid < H1 + H2) {
        const int o = tid - H1;
        const float s = g2[m*H2 + o] * rsqrtf(v2[m*H2 + o] + EPS);
        ((float4*)(blob + BLOB_DEW))[o] = make_float4(
            s, s * (b2[m*H2 + o] - m2[m*H2 + o]) + be2[m*H2 + o],
            W3[m*H2 + o], 0.0f);
    } else if (tid == H1 + H2) {
        ((float*)(blob + BLOB_B3))[0] = b3[m];
    }
}

__global__ __launch_bounds__(256, 3) void nam_mma_kernel(
    const float* __restrict__ x,
    const float* __restrict__ Wout,
    float* __restrict__ out)
{
    __shared__ __align__(16) uint32_t smw[SMEM_W];

    const int tid  = threadIdx.x;
    const int lane = tid & 31;
    const int w    = tid >> 5;          // warp 0..7 -> rows 16w..16w+15
    const int gid  = lane >> 2;         // 0..7
    const int tig  = lane & 3;          // 0..3
    const int yoff = blockIdx.y * BT;
    const int m0   = blockIdx.x * MPB;
    const uint32_t sbase = smem_u32(smw);

    // ---- stage x tile [128][32] padded to 33 words/row ----
    float* xs = (float*)smw;
    #pragma unroll
    for (int r = 0; r < (BT * NC) / 256; r++) {
        const int i = tid + r * 256;
        const int rr = i >> 5, cc = i & 31;
        xs[rr * 33 + cc] = x[(yoff + rr) * NC + cc];
    }

    // ---- stage wouts[mi][c] = Wout[c][m0+mi] (used only in the tail) ----
    if (tid < MPB * CLS) {
        const int mi2 = tid / CLS, c = tid % CLS;
        ((float*)(smw + WOUTS_W))[tid] = Wout[c * M + m0 + mi2];
    }

    // pair indices, advanced 2 per super-iteration
    int ci, cj;
    { int rem = m0, i = 0;
      while (rem >= NC - 1 - i) { rem -= NC - 1 - i; i++; }
      ci = i; cj = i + 1 + rem; }

    // ---- prologue: fill all 4 ring slots with modules m0..m0+3 ----
    #pragma unroll
    for (int s = 0; s < 4; s++)
        cpa_blob(sbase + BUF_W(s) * 4, g_blob + (size_t)(m0 + s) * BLOB_W, tid);
    asm volatile("cp.async.wait_group 2;" ::: "memory");   // m0, m0+1 landed
    __syncthreads();

    const int r0 = 16 * w + gid;      // this thread's fragment rows
    const int r1 = r0 + 8;
    float* resb = (float*)(smw + RES_W);

    #pragma unroll 1
    for (int t = 0; t < MPB / 2; t++) {
        const uint32_t bufA = BUF_W((2*t)     & 3);
        const uint32_t bufB = BUF_W((2*t + 1) & 3);

        const int ciA = ci, cjA = cj;
        adv_pair(ci, cj);
        const int ciB = ci, cjB = cj;
        adv_pair(ci, cj);

        const float4* ABCa = (const float4*)(smw + bufA + BLOB_ABC);
        const float4* ABCb = (const float4*)(smw + bufB + BLOB_ABC);
        const float xa0A = xs[r0 * 33 + ciA], xb0A = xs[r0 * 33 + cjA];
        const float xa1A = xs[r1 * 33 + ciA], xb1A = xs[r1 * 33 + cjA];
        const float xa0B = xs[r0 * 33 + ciB], xb0B = xs[r0 * 33 + cjB];
        const float xa1B = xs[r1 * 33 + ciB], xb1B = xs[r1 * 33 + cjB];

        float cfA[4][4], cfB[4][4];
        #pragma unroll
        for (int nt = 0; nt < 4; nt++)
            #pragma unroll
            for (int j = 0; j < 4; j++) { cfA[nt][j] = 0.0f; cfB[nt][j] = 0.0f; }

        // ---- two modules interleaved at the k-step level ----
        #pragma unroll
        for (int ks = 0; ks < 4; ks++) {
            const int k0 = 16 * ks + 2 * tig;
            {   // module A
                const float4 cA = ABCa[k0];
                const float4 cB = ABCa[k0 + 1];
                const float4 cC = ABCa[k0 + 8];
                const float4 cD = ABCa[k0 + 9];
                const uint32_t a0 = f16x2(relu_aff(cB, xa0A, xb0A), relu_aff(cA, xa0A, xb0A));
                const uint32_t a1 = f16x2(relu_aff(cB, xa1A, xb1A), relu_aff(cA, xa1A, xb1A));
                const uint32_t a2 = f16x2(relu_aff(cD, xa0A, xb0A), relu_aff(cC, xa0A, xb0A));
                const uint32_t a3 = f16x2(relu_aff(cD, xa1A, xb1A), relu_aff(cC, xa1A, xb1A));
                #pragma unroll
                for (int nt = 0; nt < 4; nt++) {
                    const uint2 bf = *((const uint2*)(smw + bufA + (ks*4 + nt)*66 + lane*2));
                    mma16816(cfA[nt], a0, a1, a2, a3, bf.x, bf.y);
                }
            }
            {   // module B
                const float4 cA = ABCb[k0];
                const float4 cB = ABCb[k0 + 1];
                const float4 cC = ABCb[k0 + 8];
                const float4 cD = ABCb[k0 + 9];
                const uint32_t a0 = f16x2(relu_aff(cB, xa0B, xb0B), relu_aff(cA, xa0B, xb0B));
                const uint32_t a1 = f16x2(relu_aff(cB, xa1B, xb1B), relu_aff(cA, xa1B, xb1B));
                const uint32_t a2 = f16x2(relu_aff(cD, xa0B, xb0B), relu_aff(cC, xa0B, xb0B));
                const uint32_t a3 = f16x2(relu_aff(cD, xa1B, xb1B), relu_aff(cC, xa1B, xb1B));
                #pragma unroll
                for (int nt = 0; nt < 4; nt++) {
                    const uint2 bf = *((const uint2*)(smw + bufB + (ks*4 + nt)*66 + lane*2));
                    mma16816(cfB[nt], a0, a1, a2, a3, bf.x, bf.y);
                }
            }
        }

        // ---- epilogues (independent shfl chains interleave) ----
        {
            const float4* DEW = (const float4*)(smw + bufA + BLOB_DEW);
            float p0 = 0.0f, p1 = 0.0f;
            #pragma unroll
            for (int nt = 0; nt < 4; nt++) {
                const int n0 = 8*nt + 2*tig;
                const float4 d0 = DEW[n0];
                const float4 d1 = DEW[n0 + 1];
                p0 = fmaf(d0.z, fmaxf(fmaf(d0.x, cfA[nt][0], d0.y), 0.0f), p0);
                p0 = fmaf(d1.z, fmaxf(fmaf(d1.x, cfA[nt][1], d1.y), 0.0f), p0);
                p1 = fmaf(d0.z, fmaxf(fmaf(d0.x, cfA[nt][2], d0.y), 0.0f), p1);
                p1 = fmaf(d1.z, fmaxf(fmaf(d1.x, cfA[nt][3], d1.y), 0.0f), p1);
            }
            p0 += __shfl_xor_sync(0xffffffffu, p0, 1);
            p0 += __shfl_xor_sync(0xffffffffu, p0, 2);
            p1 += __shfl_xor_sync(0xffffffffu, p1, 1);
            p1 += __shfl_xor_sync(0xffffffffu, p1, 2);
            if (tig == 0) {
                const float b3s = ((const float*)(smw + bufA + BLOB_B3))[0];
                resb[(2*t) * BT + r0] = b3s + p0;
                resb[(2*t) * BT + r1] = b3s + p1;
            }
        }
        {
            const float4* DEW = (const float4*)(smw + bufB + BLOB_DEW);
            float p0 = 0.0f, p1 = 0.0f;
            #pragma unroll
            for (int nt = 0; nt < 4; nt++) {
                const int n0 = 8*nt + 2*tig;
                const float4 d0 = DEW[n0];
                const float4 d1 = DEW[n0 + 1];
                p0 = fmaf(d0.z, fmaxf(fmaf(d0.x, cfB[nt][0], d0.y), 0.0f), p0);
                p0 = fmaf(d1.z, fmaxf(fmaf(d1.x, cfB[nt][1], d1.y), 0.0f), p0);
                p1 = fmaf(d0.z, fmaxf(fmaf(d0.x, cfB[nt][2], d0.y), 0.0f), p1);
                p1 = fmaf(d1.z, fmaxf(fmaf(d1.x, cfB[nt][3], d1.y), 0.0f), p1);
            }
            p0 += __shfl_xor_sync(0xffffffffu, p0, 1);
            p0 += __shfl_xor_sync(0xffffffffu, p0, 2);
            p1 += __shfl_xor_sync(0xffffffffu, p1, 1);
            p1 += __shfl_xor_sync(0xffffffffu, p1, 2);
            if (tig == 0) {
                const float b3s = ((const float*)(smw + bufB + BLOB_B3))[0];
                resb[(2*t + 1) * BT + r0] = b3s + p0;
                resb[(2*t + 1) * BT + r1] = b3s + p1;
            }
        }

        // copies for the NEXT super-iteration's modules must have landed
        asm volatile("cp.async.wait_group 0;" ::: "memory");
        __syncthreads();
        // refill the two slots just consumed with modules 2t+4, 2t+5
        if (2*t + 5 < MPB) {
            cpa_blob(sbase + bufA * 4, g_blob + (size_t)(m0 + 2*t + 4) * BLOB_W, tid);
            cpa_blob(sbase + bufB * 4, g_blob + (size_t)(m0 + 2*t + 5) * BLOB_W, tid);
        }
    }

    // ---- in-block head tail: 256 threads = (row, c-half); 31-dup atomics ----
    {
        const int row = tid & 127;
        const int c0  = (tid >> 7) * 5;           // 0 or 5
        const float* wo = (const float*)(smw + WOUTS_W);
        float acc[5] = {0.0f, 0.0f, 0.0f, 0.0f, 0.0f};
        #pragma unroll
        for (int mi2 = 0; mi2 < MPB; mi2++) {
            const float g = resb[mi2 * BT + row];
            #pragma unroll
            for (int c = 0; c < 5; c++)
                acc[c] = fmaf(g, wo[mi2 * CLS + c0 + c], acc[c]);
        }
        float* dst = out + (size_t)(yoff + row) * CLS + c0;
        #pragma unroll
        for (int c = 0; c < 5; c++) atomicAdd(&dst[c], acc[c]);
    }
}

extern "C" void kernel_launch(void* const* d_in, const int* in_sizes, int n_in,
                              void* d_out, int out_size)
{
    // metadata order: x, pair_idx, W1, b1, g1, be1, m1, v1,
    //                 W2, b2, g2, be2, m2, v2, W3, b3, Wout, bout
    const float* x    = (const float*)d_in[0];
    // d_in[1] = pair_idx — intentionally unused (computed analytically on device)
    const float* W1   = (const float*)d_in[2];
    const float* b1   = (const float*)d_in[3];
    const float* g1   = (const float*)d_in[4];
    const float* be1  = (const float*)d_in[5];
    const float* m1   = (const float*)d_in[6];
    const float* v1   = (const float*)d_in[7];
    const float* W2   = (const float*)d_in[8];
    const float* b2   = (const float*)d_in[9];
    const float* g2   = (const float*)d_in[10];
    const float* be2  = (const float*)d_in[11];
    const float* m2   = (const float*)d_in[12];
    const float* v2   = (const float*)d_in[13];
    const float* W3   = (const float*)d_in[14];
    const float* b3   = (const float*)d_in[15];
    const float* Wout = (const float*)d_in[16];
    const float* bout = (const float*)d_in[17];
    float* out = (float*)d_out;

    prep_kernel<<<M, 256>>>(W1, b1, g1, be1, m1, v1,
                            W2, b2, g2, be2, m2, v2, W3, b3,
                            bout, out);
    dim3 grid(NMC, B / BT);   // (31, 16)
    nam_mma_kernel<<<grid, 256>>>(x, Wout, out);
}